// round 2
// baseline (speedup 1.0000x reference)
#include <cuda_runtime.h>
#include <cuda_bf16.h>
#include <math.h>

#define BATCH 4
#define CH 64
#define HH 192
#define WW 192
#define HWSZ (HH * WW)            // 36864
#define TAPS 9
#define MID 12
#define STDV 0.4714045207910317f  // sqrt(2)/3

// ---------------- scratch (device globals; no allocation allowed) ------------
__device__ float g_gap[BATCH * CH];                    // (B,C)
__device__ float g_cf[BATCH * CH * TAPS];              // (B,C,9) normalized
__device__ float g_s[BATCH * TAPS * HWSZ];             // (B,9,H,W) normalized
__device__ float g_act[BATCH * CH * HWSZ];             // (B,C,H,W) leaky(out)

union F2U { float2 f2; unsigned long long u; };

// ---------------- K1: global average pool -> g_gap ---------------------------
__global__ void k_gap(const float* __restrict__ x) {
    int bc = blockIdx.x;                               // b*C + c
    const float4* p = reinterpret_cast<const float4*>(x + (size_t)bc * HWSZ);
    float s = 0.f;
    for (int i = threadIdx.x; i < HWSZ / 4; i += 256) {
        float4 v = p[i];
        s += (v.x + v.y) + (v.z + v.w);
    }
    for (int o = 16; o; o >>= 1) s += __shfl_xor_sync(0xffffffffu, s, o);
    __shared__ float red[8];
    if ((threadIdx.x & 31) == 0) red[threadIdx.x >> 5] = s;
    __syncthreads();
    if (threadIdx.x == 0) {
        float t = 0.f;
        #pragma unroll
        for (int i = 0; i < 8; i++) t += red[i];
        g_gap[bc] = t * (1.f / (float)HWSZ);
    }
}

// ---------------- K2: channel branch MLP + FilterNorm -> g_cf ----------------
__global__ void k_cf(const float* __restrict__ cw1, const float* __restrict__ cb1,
                     const float* __restrict__ cw2, const float* __restrict__ cb2) {
    __shared__ float h1s[BATCH * MID];
    int tid = threadIdx.x;
    if (tid < BATCH * MID) {
        int b = tid / MID, m = tid % MID;
        float a = cb1[m];
        for (int j = 0; j < CH; j++) a += g_gap[b * CH + j] * cw1[m * CH + j];
        h1s[tid] = a > 0.f ? a : 0.f;
    }
    __syncthreads();
    int b = tid >> 6, c = tid & 63;                    // 256 threads = 4*64
    float f[TAPS];
    #pragma unroll
    for (int t = 0; t < TAPS; t++) {
        float a = cb2[c * TAPS + t];
        #pragma unroll
        for (int m = 0; m < MID; m++) a += h1s[b * MID + m] * cw2[(c * TAPS + t) * MID + m];
        f[t] = a;
    }
    float mean = 0.f;
    #pragma unroll
    for (int t = 0; t < TAPS; t++) mean += f[t];
    mean *= (1.f / 9.f);
    float var = 0.f;
    #pragma unroll
    for (int t = 0; t < TAPS; t++) { float d = f[t] - mean; var += d * d; }
    var *= (1.f / 8.f);                                // ddof=1
    float inv = STDV / (sqrtf(var) + 1e-10f);
    #pragma unroll
    for (int t = 0; t < TAPS; t++) g_cf[tid * TAPS + t] = (f[t] - mean) * inv;
}

// ---------------- K3: spatial filters 1x1 conv + FilterNorm -> g_s -----------
__global__ void k_spatial(const float* __restrict__ x, const float* __restrict__ sw,
                          const float* __restrict__ sb) {
    __shared__ float ssw[TAPS * CH];
    __shared__ float ssb[TAPS];
    int h = blockIdx.x, b = blockIdx.y, w = threadIdx.x;    // block 192 threads
    for (int i = w; i < TAPS * CH; i += WW) ssw[i] = sw[i];
    if (w < TAPS) ssb[w] = sb[w];
    __syncthreads();
    float acc[TAPS];
    #pragma unroll
    for (int t = 0; t < TAPS; t++) acc[t] = ssb[t];
    const float* xp = x + ((size_t)b * CH) * HWSZ + (size_t)h * WW + w;
    for (int c = 0; c < CH; c++) {
        float v = xp[(size_t)c * HWSZ];
        #pragma unroll
        for (int t = 0; t < TAPS; t++) acc[t] += v * ssw[t * CH + c];
    }
    float mean = 0.f;
    #pragma unroll
    for (int t = 0; t < TAPS; t++) mean += acc[t];
    mean *= (1.f / 9.f);
    float var = 0.f;
    #pragma unroll
    for (int t = 0; t < TAPS; t++) { float d = acc[t] - mean; var += d * d; }
    var *= (1.f / 8.f);
    float inv = STDV / (sqrtf(var) + 1e-10f);
    size_t hw = (size_t)h * WW + w;
    #pragma unroll
    for (int t = 0; t < TAPS; t++)
        g_s[((size_t)(b * TAPS + t)) * HWSZ + hw] = (acc[t] - mean) * inv;
}

// ---------------- K4: DDF apply (mul combine) + LeakyReLU -> g_act -----------
__global__ void k_ddf(const float* __restrict__ x) {
    __shared__ float ss[TAPS * WW];      // s row for this (b,h)
    __shared__ float sc[CH * TAPS];      // cf for this b
    __shared__ float sx[3][WW];          // 3 x rows for current channel
    int h = blockIdx.x, b = blockIdx.y, w = threadIdx.x;
    size_t hw = (size_t)h * WW + w;
    #pragma unroll
    for (int t = 0; t < TAPS; t++)
        ss[t * WW + w] = g_s[((size_t)(b * TAPS + t)) * HWSZ + hw];
    for (int i = w; i < CH * TAPS; i += WW) sc[i] = g_cf[b * CH * TAPS + i];
    for (int c = 0; c < CH; c++) {
        const float* xc = x + ((size_t)(b * CH + c)) * HWSZ;
        #pragma unroll
        for (int r = 0; r < 3; r++) {
            int hh = h + r - 1;
            sx[r][w] = (hh >= 0 && hh < HH) ? xc[(size_t)hh * WW + w] : 0.f;
        }
        __syncthreads();
        float acc = 0.f;
        #pragma unroll
        for (int idx = 0; idx < TAPS; idx++) {
            int i = idx / 3, j = idx % 3;
            int ww = w + j - 1;
            float xv = (ww >= 0 && ww < WW) ? sx[i][ww] : 0.f;
            acc += xv * (ss[idx * WW + w] * sc[c * TAPS + idx]);
        }
        float a = acc >= 0.f ? acc : 0.1f * acc;
        g_act[((size_t)(b * CH + c)) * HWSZ + hw] = a;
        __syncthreads();
    }
}

// ---------------- K5: 1x9 conv (64->64, pad 4) + bias + residual -------------
// Packed f32x2 FMA over output-channel pairs. Block = (b, h, 16-o chunk).
// Reads g_act DIRECTLY as a device symbol (passing its address from host was
// the round-1 bug: host-side decay of a __device__ symbol is not the device
// address).
#define SA_FLOATS (CH * 200)                   // 12800
#define WSP_U64   (576 * 8)                    // 4608 (float2 each)
#define CONV_SMEM_BYTES ((SA_FLOATS + WSP_U64 * 2) * 4)   // 88064

__global__ __launch_bounds__(256, 2)
void k_conv(const float* __restrict__ w2, const float* __restrict__ b2,
            const float* __restrict__ x, float* __restrict__ out) {
    const int oc = blockIdx.x;         // 0..3 -> o0 = 16*oc
    const int h  = blockIdx.y;
    const int b  = blockIdx.z;
    const int o0 = oc * 16;
    extern __shared__ float sm[];
    float* sa = sm;                                                  // [64][200]
    unsigned long long* wsp = reinterpret_cast<unsigned long long*>(sm + SA_FLOATS);
    int tid = threadIdx.x;

    // fill activation row (index i = w + 4; zeros in halo)
    for (int idx = tid; idx < SA_FLOATS; idx += 256) {
        int c = idx / 200, i = idx % 200;
        int w = i - 4;
        float v = 0.f;
        if (w >= 0 && w < WW)
            v = g_act[(((size_t)(b * CH + c)) * HH + h) * WW + w];
        sa[idx] = v;
    }
    // fill weight pairs: wsp[(c*9+k)*8 + p] = {w2[o0+2p][c][k], w2[o0+2p+1][c][k]}
    for (int idx = tid; idx < WSP_U64; idx += 256) {
        int ck = idx >> 3;
        int p  = idx & 7;
        int o  = o0 + 2 * p;
        F2U t;
        t.f2 = make_float2(w2[(size_t)o * 576 + ck], w2[((size_t)o + 1) * 576 + ck]);
        wsp[idx] = t.u;
    }
    __syncthreads();

    const int wwarp = tid >> 5;
    const int l = tid & 31;
    const int p = l & 7;
    const int u = l >> 3;
    const int w0 = wwarp * 24 + u * 6;       // first output w of this lane

    unsigned long long acc[6];
    #pragma unroll
    for (int t = 0; t < 6; t++) acc[t] = 0ull;

    for (int c = 0; c < CH; c++) {
        const float* row = sa + c * 200;
        unsigned long long sp[14];           // splats of a[w0-4 .. w0+9]
        #pragma unroll
        for (int m = 0; m < 14; m++) {
            float av = row[w0 + m];          // sa index = (w0-4+m)+4
            asm("mov.b64 %0, {%1, %1};" : "=l"(sp[m]) : "f"(av));
        }
        const unsigned long long* wrow = wsp + (c * 9) * 8 + p;
        #pragma unroll
        for (int k = 0; k < TAPS; k++) {
            unsigned long long wv = wrow[k * 8];
            #pragma unroll
            for (int t = 0; t < 6; t++) {
                // out[w0+t] needs a[w0+t+k-4] = sp[t+k]
                asm("fma.rn.f32x2 %0, %1, %2, %0;" : "+l"(acc[t]) : "l"(sp[t + k]), "l"(wv));
            }
        }
    }

    __syncthreads();                          // done reading sa
    // stage results in smem for coalesced global write
    float* so = sm;                           // 16*194 = 3104 floats
    #pragma unroll
    for (int t = 0; t < 6; t++) {
        float lo, hi;
        asm("mov.b64 {%0, %1}, %2;" : "=f"(lo), "=f"(hi) : "l"(acc[t]));
        so[(2 * p    ) * 194 + w0 + t] = lo;
        so[(2 * p + 1) * 194 + w0 + t] = hi;
    }
    __syncthreads();
    for (int idx = tid; idx < 16 * WW; idx += 256) {
        int ol = idx / WW, w = idx % WW;
        int o = o0 + ol;
        size_t gi = (((size_t)(b * CH + o)) * HH + h) * WW + w;
        out[gi] = x[gi] + b2[o] + so[ol * 194 + w];
    }
}

// ---------------- launch ------------------------------------------------------
extern "C" void kernel_launch(void* const* d_in, const int* in_sizes, int n_in,
                              void* d_out, int out_size) {
    const float* x   = (const float*)d_in[0];
    const float* sw  = (const float*)d_in[1];
    const float* sb  = (const float*)d_in[2];
    const float* cw1 = (const float*)d_in[3];
    const float* cb1 = (const float*)d_in[4];
    const float* cw2 = (const float*)d_in[5];
    const float* cb2 = (const float*)d_in[6];
    const float* w2  = (const float*)d_in[7];
    const float* b2  = (const float*)d_in[8];
    float* out = (float*)d_out;

    cudaFuncSetAttribute(k_conv, cudaFuncAttributeMaxDynamicSharedMemorySize,
                         CONV_SMEM_BYTES);

    k_gap<<<BATCH * CH, 256>>>(x);
    k_cf<<<1, 256>>>(cw1, cb1, cw2, cb2);
    k_spatial<<<dim3(HH, BATCH), WW>>>(x, sw, sb);
    k_ddf<<<dim3(HH, BATCH), WW>>>(x);
    k_conv<<<dim3(4, HH, BATCH), 256, CONV_SMEM_BYTES>>>(w2, b2, x, out);
}

// round 6
// speedup vs baseline: 1.4705x; 1.4705x over previous
#include <cuda_runtime.h>
#include <cuda_bf16.h>
#include <cstdint>
#include <math.h>

#define BATCH 4
#define CH 64
#define HH 192
#define WW 192
#define HWSZ (HH * WW)            // 36864
#define TAPS 9
#define MID 12
#define STDV 0.4714045207910317f  // sqrt(2)/3

// ---------------- scratch (device globals; no allocation allowed) ------------
__device__ float g_gap[BATCH * CH];
__device__ float g_cf[BATCH * CH * TAPS];
__device__ float g_s[BATCH * TAPS * HWSZ];
__device__ float g_act[BATCH * CH * HWSZ];     // leaky(out), tf32-rounded
__device__ float g_wt[72 * 4 * 32 * 4];        // fragment-ordered tf32 weights (147KB)

// ---------------- K0: weight prep into mma fragment order --------------------
// Layout: g_wt[((ks*4 + mf)*32 + lane)*4 + reg], ks = k*8 + cc (k-major).
// reg0: o=mf*16+g,   c=cc*8+m     reg1: o=+8, c same
// reg2: o=mf*16+g,   c=cc*8+m+4   reg3: o=+8, c same     (g=lane>>2, m=lane&3)
__global__ void k_wprep(const float* __restrict__ w2) {
    int idx = blockIdx.x * 256 + threadIdx.x;          // 36864 total
    if (idx >= 72 * 4 * 32 * 4) return;
    int reg  = idx & 3;
    int lane = (idx >> 2) & 31;
    int mf   = (idx >> 7) & 3;
    int ks   = idx >> 9;
    int k = ks >> 3, cc = ks & 7;
    int g = lane >> 2, m = lane & 3;
    int o = mf * 16 + g + ((reg & 1) ? 8 : 0);
    int c = cc * 8 + m + ((reg >> 1) ? 4 : 0);
    float v = w2[(size_t)o * 576 + c * 9 + k];
    uint32_t u; asm("cvt.rna.tf32.f32 %0, %1;" : "=r"(u) : "f"(v));
    g_wt[idx] = __uint_as_float(u);
}

// ---------------- K1: global average pool -> g_gap ---------------------------
__global__ void k_gap(const float* __restrict__ x) {
    int bc = blockIdx.x;
    const float4* p = reinterpret_cast<const float4*>(x + (size_t)bc * HWSZ);
    float s = 0.f;
    for (int i = threadIdx.x; i < HWSZ / 4; i += 256) {
        float4 v = p[i];
        s += (v.x + v.y) + (v.z + v.w);
    }
    for (int o = 16; o; o >>= 1) s += __shfl_xor_sync(0xffffffffu, s, o);
    __shared__ float red[8];
    if ((threadIdx.x & 31) == 0) red[threadIdx.x >> 5] = s;
    __syncthreads();
    if (threadIdx.x == 0) {
        float t = 0.f;
        #pragma unroll
        for (int i = 0; i < 8; i++) t += red[i];
        g_gap[bc] = t * (1.f / (float)HWSZ);
    }
}

// ---------------- K2: channel branch MLP + FilterNorm -> g_cf ----------------
__global__ void k_cf(const float* __restrict__ cw1, const float* __restrict__ cb1,
                     const float* __restrict__ cw2, const float* __restrict__ cb2) {
    __shared__ float h1s[BATCH * MID];
    int tid = threadIdx.x;
    if (tid < BATCH * MID) {
        int b = tid / MID, m = tid % MID;
        float a = cb1[m];
        for (int j = 0; j < CH; j++) a += g_gap[b * CH + j] * cw1[m * CH + j];
        h1s[tid] = a > 0.f ? a : 0.f;
    }
    __syncthreads();
    int b = tid >> 6, c = tid & 63;
    float f[TAPS];
    #pragma unroll
    for (int t = 0; t < TAPS; t++) {
        float a = cb2[c * TAPS + t];
        #pragma unroll
        for (int m = 0; m < MID; m++) a += h1s[b * MID + m] * cw2[(c * TAPS + t) * MID + m];
        f[t] = a;
    }
    float mean = 0.f;
    #pragma unroll
    for (int t = 0; t < TAPS; t++) mean += f[t];
    mean *= (1.f / 9.f);
    float var = 0.f;
    #pragma unroll
    for (int t = 0; t < TAPS; t++) { float d = f[t] - mean; var += d * d; }
    var *= (1.f / 8.f);
    float inv = STDV / (sqrtf(var) + 1e-10f);
    #pragma unroll
    for (int t = 0; t < TAPS; t++) g_cf[tid * TAPS + t] = (f[t] - mean) * inv;
}

// ---------------- K3: spatial filters 1x1 conv + FilterNorm -> g_s -----------
__global__ void k_spatial(const float* __restrict__ x, const float* __restrict__ sw,
                          const float* __restrict__ sb) {
    __shared__ float ssw[TAPS * CH];
    __shared__ float ssb[TAPS];
    int h = blockIdx.x, b = blockIdx.y, w = threadIdx.x;
    for (int i = w; i < TAPS * CH; i += WW) ssw[i] = sw[i];
    if (w < TAPS) ssb[w] = sb[w];
    __syncthreads();
    float acc[TAPS];
    #pragma unroll
    for (int t = 0; t < TAPS; t++) acc[t] = ssb[t];
    const float* xp = x + ((size_t)b * CH) * HWSZ + (size_t)h * WW + w;
    for (int c = 0; c < CH; c++) {
        float v = xp[(size_t)c * HWSZ];
        #pragma unroll
        for (int t = 0; t < TAPS; t++) acc[t] += v * ssw[t * CH + c];
    }
    float mean = 0.f;
    #pragma unroll
    for (int t = 0; t < TAPS; t++) mean += acc[t];
    mean *= (1.f / 9.f);
    float var = 0.f;
    #pragma unroll
    for (int t = 0; t < TAPS; t++) { float d = acc[t] - mean; var += d * d; }
    var *= (1.f / 8.f);
    float inv = STDV / (sqrtf(var) + 1e-10f);
    size_t hw = (size_t)h * WW + w;
    #pragma unroll
    for (int t = 0; t < TAPS; t++)
        g_s[((size_t)(b * TAPS + t)) * HWSZ + hw] = (acc[t] - mean) * inv;
}

// ---------------- K4: DDF apply + LeakyReLU -> g_act (tf32-rounded) ----------
// c split in halves (grid.z=2) for occupancy; ping-pong x-row buffers.
__global__ void k_ddf(const float* __restrict__ x) {
    __shared__ float ss[TAPS * WW];
    __shared__ float sc[32 * TAPS];
    __shared__ float sx[2][3][WW];
    int h = blockIdx.x, b = blockIdx.y, c0 = blockIdx.z * 32, w = threadIdx.x;
    size_t hw = (size_t)h * WW + w;
    #pragma unroll
    for (int t = 0; t < TAPS; t++)
        ss[t * WW + w] = g_s[((size_t)(b * TAPS + t)) * HWSZ + hw];
    for (int i = w; i < 32 * TAPS; i += WW) sc[i] = g_cf[(b * CH + c0) * TAPS + i];
    {
        const float* xc = x + ((size_t)(b * CH + c0)) * HWSZ;
        #pragma unroll
        for (int r = 0; r < 3; r++) {
            int hh = h + r - 1;
            sx[0][r][w] = (hh >= 0 && hh < HH) ? xc[(size_t)hh * WW + w] : 0.f;
        }
    }
    __syncthreads();
    int pb = 0;
    for (int ci = 0; ci < 32; ci++) {
        if (ci < 31) {
            const float* xc = x + ((size_t)(b * CH + c0 + ci + 1)) * HWSZ;
            #pragma unroll
            for (int r = 0; r < 3; r++) {
                int hh = h + r - 1;
                sx[pb ^ 1][r][w] = (hh >= 0 && hh < HH) ? xc[(size_t)hh * WW + w] : 0.f;
            }
        }
        float acc = 0.f;
        #pragma unroll
        for (int idx = 0; idx < TAPS; idx++) {
            int i = idx / 3, j = idx % 3, ww = w + j - 1;
            float xv = (ww >= 0 && ww < WW) ? sx[pb][i][ww] : 0.f;
            acc += xv * (ss[idx * WW + w] * sc[ci * TAPS + idx]);
        }
        float a = acc >= 0.f ? acc : 0.1f * acc;
        uint32_t u; asm("cvt.rna.tf32.f32 %0, %1;" : "=r"(u) : "f"(a));
        g_act[((size_t)(b * CH + c0 + ci)) * HWSZ + hw] = __uint_as_float(u);
        __syncthreads();
        pb ^= 1;
    }
}

// ---------------- K5: 1x9 conv via mma.sync tf32 + bias + residual -----------
// Y[o][w] = sum_{c,k} W_k[o][c] * a[c][w+k-4]. K=576 as 72 k-steps of 8 (k-major
// so each step has constant tap shift). Warp tile M=32 x N=48. B frags are
// scalar LDS from sa[c][200] (stride 200 -> conflict-free). A frags are one
// LDS.128 each from fragment-ordered g_wt image. D stays in registers.
#define W_FLOATS (72 * 4 * 32 * 4)      // 36864
#define SA_FLOATS (CH * 200)            // 12800
#define CONV_SMEM ((W_FLOATS + SA_FLOATS) * 4)   // 198656

__device__ __forceinline__ void mma8(float* d, const uint4& a, uint32_t b0, uint32_t b1) {
    asm volatile(
        "mma.sync.aligned.m16n8k8.row.col.f32.tf32.tf32.f32 "
        "{%0,%1,%2,%3}, {%4,%5,%6,%7}, {%8,%9}, {%0,%1,%2,%3};"
        : "+f"(d[0]), "+f"(d[1]), "+f"(d[2]), "+f"(d[3])
        : "r"(a.x), "r"(a.y), "r"(a.z), "r"(a.w), "r"(b0), "r"(b1));
}

__global__ __launch_bounds__(256, 1)
void k_conv(const float* __restrict__ x, const float* __restrict__ b2,
            float* __restrict__ out) {
    extern __shared__ float sm[];
    float* wf = sm;                       // [72][4][32][4]
    float* sa = sm + W_FLOATS;            // [64][200]
    __shared__ float sbias[CH];
    const int tid = threadIdx.x;
    const int warp = tid >> 5, lane = tid & 31;
    const int g = lane >> 2, m = lane & 3;
    const int mo2 = warp & 1;             // M half: o base = mo2*32
    const int nh = warp >> 1;             // N quarter: w base = nh*48
    const int w0 = nh * 48;
    const int b = blockIdx.y;

    // load weights once (hot in L2 across blocks)
    {
        const float4* src = reinterpret_cast<const float4*>(g_wt);
        float4* dst = reinterpret_cast<float4*>(wf);
        for (int i = tid; i < W_FLOATS / 4; i += 256) dst[i] = src[i];
    }
    if (tid < CH) sbias[tid] = b2[tid];

    for (int hh = 0; hh < 2; hh++) {
        const int h = blockIdx.x * 2 + hh;
        __syncthreads();                  // prev-iter smem reads done / W ready
        // fill activation row with halo: sa[c][i] = a[c][i-4], zeros outside
        const float* arow = g_act + ((size_t)b * CH) * HWSZ + (size_t)h * WW;
        for (int idx = tid; idx < SA_FLOATS; idx += 256) {
            int c = idx / 200, i = idx - c * 200;
            int w = i - 4;
            sa[idx] = (w >= 0 && w < WW) ? arow[(size_t)c * HWSZ + w] : 0.f;
        }
        __syncthreads();

        float acc[2][6][4];
        #pragma unroll
        for (int mf = 0; mf < 2; mf++)
            #pragma unroll
            for (int j = 0; j < 6; j++)
                #pragma unroll
                for (int r = 0; r < 4; r++) acc[mf][j][r] = 0.f;

        for (int k = 0; k < TAPS; k++) {
            #pragma unroll
            for (int cc = 0; cc < 8; cc++) {
                const int ks = k * 8 + cc;
                const uint4* wfrag = reinterpret_cast<const uint4*>(
                    wf + ((ks * 4 + mo2 * 2) * 32 + lane) * 4);
                uint4 a0 = wfrag[0];
                uint4 a1 = wfrag[32];
                const float* sb0 = sa + (cc * 8 + m) * 200 + (w0 + g + k);
                const float* sb1 = sb0 + 4 * 200;
                #pragma unroll
                for (int j = 0; j < 6; j++) {
                    uint32_t bb0 = __float_as_uint(sb0[8 * j]);
                    uint32_t bb1 = __float_as_uint(sb1[8 * j]);
                    mma8(acc[0][j], a0, bb0, bb1);
                    mma8(acc[1][j], a1, bb0, bb1);
                }
            }
        }

        // epilogue: residual + bias, float2 stores (w even -> aligned)
        const size_t rbase = ((size_t)b * CH) * HWSZ + (size_t)h * WW;
        #pragma unroll
        for (int mf = 0; mf < 2; mf++) {
            const int o = mo2 * 32 + mf * 16 + g;
            #pragma unroll
            for (int j = 0; j < 6; j++) {
                const int w = w0 + 8 * j + 2 * m;
                size_t i0 = rbase + (size_t)o * HWSZ + w;
                float2 xv = *reinterpret_cast<const float2*>(x + i0);
                float2 r0;
                r0.x = xv.x + sbias[o] + acc[mf][j][0];
                r0.y = xv.y + sbias[o] + acc[mf][j][1];
                *reinterpret_cast<float2*>(out + i0) = r0;
                size_t i1 = i0 + (size_t)8 * HWSZ;
                float2 xv1 = *reinterpret_cast<const float2*>(x + i1);
                float2 r1;
                r1.x = xv1.x + sbias[o + 8] + acc[mf][j][2];
                r1.y = xv1.y + sbias[o + 8] + acc[mf][j][3];
                *reinterpret_cast<float2*>(out + i1) = r1;
            }
        }
    }
}

// ---------------- launch ------------------------------------------------------
extern "C" void kernel_launch(void* const* d_in, const int* in_sizes, int n_in,
                              void* d_out, int out_size) {
    const float* x   = (const float*)d_in[0];
    const float* sw  = (const float*)d_in[1];
    const float* sb  = (const float*)d_in[2];
    const float* cw1 = (const float*)d_in[3];
    const float* cb1 = (const float*)d_in[4];
    const float* cw2 = (const float*)d_in[5];
    const float* cb2 = (const float*)d_in[6];
    const float* w2  = (const float*)d_in[7];
    const float* b2  = (const float*)d_in[8];
    float* out = (float*)d_out;

    cudaFuncSetAttribute(k_conv, cudaFuncAttributeMaxDynamicSharedMemorySize, CONV_SMEM);

    k_wprep<<<144, 256>>>(w2);
    k_gap<<<BATCH * CH, 256>>>(x);
    k_cf<<<1, 256>>>(cw1, cb1, cw2, cb2);
    k_spatial<<<dim3(HH, BATCH), WW>>>(x, sw, sb);
    k_ddf<<<dim3(HH, BATCH, 2), WW>>>(x);
    k_conv<<<dim3(HH / 2, BATCH), 256, CONV_SMEM>>>(x, b2, out);
}

// round 7
// speedup vs baseline: 3.0678x; 2.0862x over previous
#include <cuda_runtime.h>
#include <cuda_bf16.h>
#include <cuda_fp16.h>
#include <cstdint>
#include <math.h>

#define BATCH 4
#define CH 64
#define HH 192
#define WW 192
#define HWSZ (HH * WW)            // 36864
#define TAPS 9
#define MID 12
#define STDV 0.4714045207910317f  // sqrt(2)/3

// ---------------- scratch (device globals; no allocation allowed) ------------
__device__ float g_gapp[4 * BATCH * CH];          // partial GAP sums
__device__ float g_cf[BATCH * CH * TAPS];
__device__ float g_s[BATCH * TAPS * HWSZ];
__device__ __half g_acth[BATCH * CH * HWSZ];      // leaky(out), fp16
__device__ uint32_t g_wtf[36 * 4 * 32 * 4];       // fragment-ordered fp16x2 weights

// ---------------- K0: weight prep into m16n8k16 fp16 fragment order ----------
// g_wtf[((ks*4+mf)*32+lane)*4+reg], ks = tap*4+cc (k-major).
// A frag (16x16): a0={A[g][2t],A[g][2t+1]} a1={A[g+8][..]} a2={A[g][2t+8,+9]} a3={A[g+8][2t+8,+9]}
// A row = o (mf*16 base), A col = channel cc*16 base.
__global__ void k_wprep(const float* __restrict__ w2) {
    int idx = blockIdx.x * 256 + threadIdx.x;     // 18432 total
    if (idx >= 36 * 4 * 32 * 4) return;
    int reg  = idx & 3;
    int lane = (idx >> 2) & 31;
    int mf   = (idx >> 7) & 3;
    int ks   = idx >> 9;
    int tap = ks >> 2, cc = ks & 3;
    int g = lane >> 2, t = lane & 3;
    int o = mf * 16 + g + ((reg & 1) ? 8 : 0);
    int c = cc * 16 + 2 * t + ((reg & 2) ? 8 : 0);
    float lo = w2[(size_t)o * 576 + c * 9 + tap];
    float hi = w2[(size_t)o * 576 + (c + 1) * 9 + tap];
    __half2 hv = __halves2half2(__float2half(lo), __float2half(hi));
    g_wtf[idx] = *reinterpret_cast<uint32_t*>(&hv);
}

// ---------------- K1: partial global average pool ----------------------------
__global__ void k_gap(const float* __restrict__ x) {
    int bc = blockIdx.x, q = blockIdx.y;          // quarter of the plane
    const float4* p = reinterpret_cast<const float4*>(x + (size_t)bc * HWSZ) + q * 2304;
    float s = 0.f;
    for (int i = threadIdx.x; i < 2304; i += 256) {
        float4 v = p[i];
        s += (v.x + v.y) + (v.z + v.w);
    }
    for (int o = 16; o; o >>= 1) s += __shfl_xor_sync(0xffffffffu, s, o);
    __shared__ float red[8];
    if ((threadIdx.x & 31) == 0) red[threadIdx.x >> 5] = s;
    __syncthreads();
    if (threadIdx.x == 0) {
        float t = 0.f;
        #pragma unroll
        for (int i = 0; i < 8; i++) t += red[i];
        g_gapp[q * (BATCH * CH) + bc] = t;
    }
}

// ---------------- K2: channel branch MLP + FilterNorm -> g_cf ----------------
__global__ void k_cf(const float* __restrict__ cw1, const float* __restrict__ cb1,
                     const float* __restrict__ cw2, const float* __restrict__ cb2) {
    __shared__ float gs[BATCH * CH];
    __shared__ float h1s[BATCH * MID];
    int tid = threadIdx.x;
    gs[tid] = (g_gapp[tid] + g_gapp[256 + tid] + g_gapp[512 + tid] + g_gapp[768 + tid])
              * (1.f / (float)HWSZ);
    __syncthreads();
    if (tid < BATCH * MID) {
        int b = tid / MID, m = tid % MID;
        float a = cb1[m];
        for (int j = 0; j < CH; j++) a += gs[b * CH + j] * cw1[m * CH + j];
        h1s[tid] = a > 0.f ? a : 0.f;
    }
    __syncthreads();
    int b = tid >> 6, c = tid & 63;
    float f[TAPS];
    #pragma unroll
    for (int t = 0; t < TAPS; t++) {
        float a = cb2[c * TAPS + t];
        #pragma unroll
        for (int m = 0; m < MID; m++) a += h1s[b * MID + m] * cw2[(c * TAPS + t) * MID + m];
        f[t] = a;
    }
    float mean = 0.f;
    #pragma unroll
    for (int t = 0; t < TAPS; t++) mean += f[t];
    mean *= (1.f / 9.f);
    float var = 0.f;
    #pragma unroll
    for (int t = 0; t < TAPS; t++) { float d = f[t] - mean; var += d * d; }
    var *= (1.f / 8.f);
    float inv = STDV / (sqrtf(var) + 1e-10f);
    #pragma unroll
    for (int t = 0; t < TAPS; t++) g_cf[tid * TAPS + t] = (f[t] - mean) * inv;
}

// ---------------- K3: spatial filters, c-split x2 + FilterNorm -> g_s --------
__global__ void k_spatial(const float* __restrict__ x, const float* __restrict__ sw,
                          const float* __restrict__ sb) {
    __shared__ float ssw[TAPS * CH];
    __shared__ float ssb[TAPS];
    __shared__ float sp[2][TAPS][WW];
    int h = blockIdx.x, b = blockIdx.y;
    int tid = threadIdx.x;                        // 384 threads
    int p = tid / WW, w = tid - p * WW;
    for (int i = tid; i < TAPS * CH; i += 384) ssw[i] = sw[i];
    if (tid < TAPS) ssb[tid] = sb[tid];
    __syncthreads();
    float acc[TAPS];
    #pragma unroll
    for (int t = 0; t < TAPS; t++) acc[t] = 0.f;
    const float* xp = x + ((size_t)(b * CH + p * 32)) * HWSZ + (size_t)h * WW + w;
    #pragma unroll 4
    for (int c = 0; c < 32; c++) {
        float v = xp[(size_t)c * HWSZ];
        #pragma unroll
        for (int t = 0; t < TAPS; t++) acc[t] += v * ssw[t * CH + p * 32 + c];
    }
    #pragma unroll
    for (int t = 0; t < TAPS; t++) sp[p][t][w] = acc[t];
    __syncthreads();
    if (tid < WW) {
        float f[TAPS];
        #pragma unroll
        for (int t = 0; t < TAPS; t++) f[t] = sp[0][t][tid] + sp[1][t][tid] + ssb[t];
        float mean = 0.f;
        #pragma unroll
        for (int t = 0; t < TAPS; t++) mean += f[t];
        mean *= (1.f / 9.f);
        float var = 0.f;
        #pragma unroll
        for (int t = 0; t < TAPS; t++) { float d = f[t] - mean; var += d * d; }
        var *= (1.f / 8.f);
        float inv = STDV / (sqrtf(var) + 1e-10f);
        size_t hw = (size_t)h * WW + tid;
        #pragma unroll
        for (int t = 0; t < TAPS; t++)
            g_s[((size_t)(b * TAPS + t)) * HWSZ + hw] = (f[t] - mean) * inv;
    }
}

// ---------------- K4: DDF apply + LeakyReLU -> g_acth (fp16) -----------------
__global__ void k_ddf(const float* __restrict__ x) {
    __shared__ float ss[TAPS * WW];
    __shared__ float sc[32 * TAPS];
    __shared__ float sx[2][3][WW];
    int h = blockIdx.x, b = blockIdx.y, c0 = blockIdx.z * 32, w = threadIdx.x;
    size_t hw = (size_t)h * WW + w;
    #pragma unroll
    for (int t = 0; t < TAPS; t++)
        ss[t * WW + w] = g_s[((size_t)(b * TAPS + t)) * HWSZ + hw];
    for (int i = w; i < 32 * TAPS; i += WW) sc[i] = g_cf[(b * CH + c0) * TAPS + i];
    {
        const float* xc = x + ((size_t)(b * CH + c0)) * HWSZ;
        #pragma unroll
        for (int r = 0; r < 3; r++) {
            int hh = h + r - 1;
            sx[0][r][w] = (hh >= 0 && hh < HH) ? xc[(size_t)hh * WW + w] : 0.f;
        }
    }
    __syncthreads();
    int pb = 0;
    for (int ci = 0; ci < 32; ci++) {
        if (ci < 31) {
            const float* xc = x + ((size_t)(b * CH + c0 + ci + 1)) * HWSZ;
            #pragma unroll
            for (int r = 0; r < 3; r++) {
                int hh = h + r - 1;
                sx[pb ^ 1][r][w] = (hh >= 0 && hh < HH) ? xc[(size_t)hh * WW + w] : 0.f;
            }
        }
        float acc = 0.f;
        #pragma unroll
        for (int idx = 0; idx < TAPS; idx++) {
            int i = idx / 3, j = idx % 3, ww = w + j - 1;
            float xv = (ww >= 0 && ww < WW) ? sx[pb][i][ww] : 0.f;
            acc += xv * (ss[idx * WW + w] * sc[ci * TAPS + idx]);
        }
        float a = acc >= 0.f ? acc : 0.1f * acc;
        g_acth[((size_t)(b * CH + c0 + ci)) * HWSZ + hw] = __float2half(a);
        __syncthreads();
        pb ^= 1;
    }
}

// ---------------- K5: 1x9 conv via mma.sync fp16 + bias + residual -----------
// K=576 as 36 k-steps of 16 (k-major per tap -> constant shift). Warp M=32,N=48.
// B frags: LDS.32 of channel-pair half2 from sa2[32][200] (conflict-free).
// A frags: LDS.128 from fragment-ordered weight image.
#define WF_U32 (36 * 4 * 32 * 4)       // 18432
#define SA_U32 (32 * 200)              // 6400
#define CONV_SMEM ((WF_U32 + SA_U32) * 4)   // 99328

__device__ __forceinline__ void mma16(float* d, const uint4& a, uint32_t b0, uint32_t b1) {
    asm volatile(
        "mma.sync.aligned.m16n8k16.row.col.f32.f16.f16.f32 "
        "{%0,%1,%2,%3}, {%4,%5,%6,%7}, {%8,%9}, {%0,%1,%2,%3};"
        : "+f"(d[0]), "+f"(d[1]), "+f"(d[2]), "+f"(d[3])
        : "r"(a.x), "r"(a.y), "r"(a.z), "r"(a.w), "r"(b0), "r"(b1));
}

__global__ __launch_bounds__(256, 2)
void k_conv(const float* __restrict__ x, const float* __restrict__ b2,
            float* __restrict__ out) {
    extern __shared__ uint32_t smu[];
    uint32_t* wfu = smu;                       // [36][4][32][4] fp16x2
    uint32_t* sau = smu + WF_U32;              // [32 c-pairs][200] fp16x2
    __shared__ float sbias[CH];
    const int tid = threadIdx.x;
    const int warp = tid >> 5, lane = tid & 31;
    const int g = lane >> 2, t = lane & 3;
    const int mo2 = warp & 1;                  // o base = mo2*32
    const int nh = warp >> 1;
    const int w0 = nh * 48;
    const int b = blockIdx.y;

    {
        const uint4* src = reinterpret_cast<const uint4*>(g_wtf);
        uint4* dst = reinterpret_cast<uint4*>(wfu);
        for (int i = tid; i < WF_U32 / 4; i += 256) dst[i] = src[i];
    }
    if (tid < CH) sbias[tid] = b2[tid];

    for (int hh = 0; hh < 2; hh++) {
        const int h = blockIdx.x * 2 + hh;
        __syncthreads();
        // fill sa2: channel-pair half2 with halo (i = w+4)
        const __half* arow = g_acth + ((size_t)b * CH) * HWSZ + (size_t)h * WW;
        for (int idx = tid; idx < SA_U32; idx += 256) {
            int c2 = idx / 200, i = idx - c2 * 200;
            int w = i - 4;
            __half2 hv;
            if (w >= 0 && w < WW)
                hv = __halves2half2(arow[(size_t)(2 * c2) * HWSZ + w],
                                    arow[(size_t)(2 * c2 + 1) * HWSZ + w]);
            else
                hv = __halves2half2(__float2half(0.f), __float2half(0.f));
            sau[idx] = *reinterpret_cast<uint32_t*>(&hv);
        }
        __syncthreads();

        float acc[2][6][4];
        #pragma unroll
        for (int mf = 0; mf < 2; mf++)
            #pragma unroll
            for (int j = 0; j < 6; j++)
                #pragma unroll
                for (int r = 0; r < 4; r++) acc[mf][j][r] = 0.f;

        for (int tap = 0; tap < TAPS; tap++) {
            #pragma unroll
            for (int cc = 0; cc < 4; cc++) {
                const int ks = tap * 4 + cc;
                const uint4* wp = reinterpret_cast<const uint4*>(
                    wfu + ((ks * 4 + mo2 * 2) * 32 + lane) * 4);
                uint4 a0 = wp[0];
                uint4 a1 = wp[32];
                const uint32_t* pb0 = sau + (cc * 8 + t) * 200 + (w0 + g + tap);
                const uint32_t* pb1 = pb0 + 4 * 200;
                #pragma unroll
                for (int j = 0; j < 6; j++) {
                    uint32_t bb0 = pb0[8 * j];
                    uint32_t bb1 = pb1[8 * j];
                    mma16(acc[0][j], a0, bb0, bb1);
                    mma16(acc[1][j], a1, bb0, bb1);
                }
            }
        }

        // epilogue: residual + bias (D: rows g/g+8, cols 2t,2t+1)
        const size_t rbase = ((size_t)b * CH) * HWSZ + (size_t)h * WW;
        #pragma unroll
        for (int mf = 0; mf < 2; mf++) {
            const int o = mo2 * 32 + mf * 16 + g;
            #pragma unroll
            for (int j = 0; j < 6; j++) {
                const int w = w0 + 8 * j + 2 * t;
                size_t i0 = rbase + (size_t)o * HWSZ + w;
                float2 xv = *reinterpret_cast<const float2*>(x + i0);
                float2 r0;
                r0.x = xv.x + sbias[o] + acc[mf][j][0];
                r0.y = xv.y + sbias[o] + acc[mf][j][1];
                *reinterpret_cast<float2*>(out + i0) = r0;
                size_t i1 = i0 + (size_t)8 * HWSZ;
                float2 xv1 = *reinterpret_cast<const float2*>(x + i1);
                float2 r1;
                r1.x = xv1.x + sbias[o + 8] + acc[mf][j][2];
                r1.y = xv1.y + sbias[o + 8] + acc[mf][j][3];
                *reinterpret_cast<float2*>(out + i1) = r1;
            }
        }
    }
}

// ---------------- launch ------------------------------------------------------
extern "C" void kernel_launch(void* const* d_in, const int* in_sizes, int n_in,
                              void* d_out, int out_size) {
    const float* x   = (const float*)d_in[0];
    const float* sw  = (const float*)d_in[1];
    const float* sb  = (const float*)d_in[2];
    const float* cw1 = (const float*)d_in[3];
    const float* cb1 = (const float*)d_in[4];
    const float* cw2 = (const float*)d_in[5];
    const float* cb2 = (const float*)d_in[6];
    const float* w2  = (const float*)d_in[7];
    const float* b2  = (const float*)d_in[8];
    float* out = (float*)d_out;

    cudaFuncSetAttribute(k_conv, cudaFuncAttributeMaxDynamicSharedMemorySize, CONV_SMEM);

    k_wprep<<<72, 256>>>(w2);
    k_gap<<<dim3(BATCH * CH, 4), 256>>>(x);
    k_cf<<<1, 256>>>(cw1, cb1, cw2, cb2);
    k_spatial<<<dim3(HH, BATCH), 384>>>(x, sw, sb);
    k_ddf<<<dim3(HH, BATCH, 2), WW>>>(x);
    k_conv<<<dim3(HH / 2, BATCH), 256, CONV_SMEM>>>(x, b2, out);
}

// round 9
// speedup vs baseline: 4.0532x; 1.3212x over previous
#include <cuda_runtime.h>
#include <cuda_bf16.h>
#include <cuda_fp16.h>
#include <cstdint>
#include <math.h>

#define BATCH 4
#define CH 64
#define HH 192
#define WW 192
#define HWSZ (HH * WW)            // 36864
#define TAPS 9
#define MID 12
#define STDV 0.4714045207910317f  // sqrt(2)/3

// ---------------- scratch (device globals; no allocation allowed) ------------
__device__ float g_gapp[4 * BATCH * CH];          // partial GAP sums
__device__ float g_cf[BATCH * CH * TAPS];
__device__ float g_s[BATCH * TAPS * HWSZ];
__device__ uint32_t g_wtf[36 * 4 * 32 * 4];       // fragment-ordered fp16x2 weights

// ---------------- K0: weight prep into m16n8k16 fp16 fragment order ----------
__global__ void k_wprep(const float* __restrict__ w2) {
    int idx = blockIdx.x * 256 + threadIdx.x;     // 18432 total
    if (idx >= 36 * 4 * 32 * 4) return;
    int reg  = idx & 3;
    int lane = (idx >> 2) & 31;
    int mf   = (idx >> 7) & 3;
    int ks   = idx >> 9;
    int tap = ks >> 2, cc = ks & 3;
    int g = lane >> 2, t = lane & 3;
    int o = mf * 16 + g + ((reg & 1) ? 8 : 0);
    int c = cc * 16 + 2 * t + ((reg & 2) ? 8 : 0);
    float lo = w2[(size_t)o * 576 + c * 9 + tap];
    float hi = w2[(size_t)o * 576 + (c + 1) * 9 + tap];
    __half2 hv = __halves2half2(__float2half(lo), __float2half(hi));
    g_wtf[idx] = *reinterpret_cast<uint32_t*>(&hv);
}

// ---------------- K1: partial global average pool ----------------------------
__global__ void k_gap(const float* __restrict__ x) {
    int bc = blockIdx.x, q = blockIdx.y;
    const float4* p = reinterpret_cast<const float4*>(x + (size_t)bc * HWSZ) + q * 2304;
    float s = 0.f;
    for (int i = threadIdx.x; i < 2304; i += 256) {
        float4 v = p[i];
        s += (v.x + v.y) + (v.z + v.w);
    }
    for (int o = 16; o; o >>= 1) s += __shfl_xor_sync(0xffffffffu, s, o);
    __shared__ float red[8];
    if ((threadIdx.x & 31) == 0) red[threadIdx.x >> 5] = s;
    __syncthreads();
    if (threadIdx.x == 0) {
        float t = 0.f;
        #pragma unroll
        for (int i = 0; i < 8; i++) t += red[i];
        g_gapp[q * (BATCH * CH) + bc] = t;
    }
}

// ---------------- K2: channel branch MLP + FilterNorm -> g_cf ----------------
__global__ void k_cf(const float* __restrict__ cw1, const float* __restrict__ cb1,
                     const float* __restrict__ cw2, const float* __restrict__ cb2) {
    __shared__ float gs[BATCH * CH];
    __shared__ float h1s[BATCH * MID];
    int tid = threadIdx.x;
    gs[tid] = (g_gapp[tid] + g_gapp[256 + tid] + g_gapp[512 + tid] + g_gapp[768 + tid])
              * (1.f / (float)HWSZ);
    __syncthreads();
    if (tid < BATCH * MID) {
        int b = tid / MID, m = tid % MID;
        float a = cb1[m];
        for (int j = 0; j < CH; j++) a += gs[b * CH + j] * cw1[m * CH + j];
        h1s[tid] = a > 0.f ? a : 0.f;
    }
    __syncthreads();
    int b = tid >> 6, c = tid & 63;
    float f[TAPS];
    #pragma unroll
    for (int t = 0; t < TAPS; t++) {
        float a = cb2[c * TAPS + t];
        #pragma unroll
        for (int m = 0; m < MID; m++) a += h1s[b * MID + m] * cw2[(c * TAPS + t) * MID + m];
        f[t] = a;
    }
    float mean = 0.f;
    #pragma unroll
    for (int t = 0; t < TAPS; t++) mean += f[t];
    mean *= (1.f / 9.f);
    float var = 0.f;
    #pragma unroll
    for (int t = 0; t < TAPS; t++) { float d = f[t] - mean; var += d * d; }
    var *= (1.f / 8.f);
    float inv = STDV / (sqrtf(var) + 1e-10f);
    #pragma unroll
    for (int t = 0; t < TAPS; t++) g_cf[tid * TAPS + t] = (f[t] - mean) * inv;
}

// ---------------- K3: spatial filters (float4, c-quarter split) -> g_s -------
__global__ void k_spatial(const float* __restrict__ x, const float* __restrict__ sw,
                          const float* __restrict__ sb) {
    __shared__ float ssw[TAPS * CH];
    __shared__ float ssb[TAPS];
    __shared__ float4 sp[4][TAPS][48];
    int h = blockIdx.x, b = blockIdx.y;
    int tid = threadIdx.x;                        // 192 threads
    int q = tid / 48, w4 = tid - q * 48;          // c-quarter, w-group of 4
    for (int i = tid; i < TAPS * CH; i += 192) ssw[i] = sw[i];
    if (tid < TAPS) ssb[tid] = sb[tid];
    __syncthreads();
    float4 acc[TAPS];
    #pragma unroll
    for (int t = 0; t < TAPS; t++) acc[t] = make_float4(0.f, 0.f, 0.f, 0.f);
    const float4* xp = reinterpret_cast<const float4*>(
        x + ((size_t)(b * CH + q * 16)) * HWSZ + (size_t)h * WW) + w4;
    #pragma unroll 2
    for (int c = 0; c < 16; c++) {
        float4 v = xp[c * (HWSZ / 4)];
        #pragma unroll
        for (int t = 0; t < TAPS; t++) {
            float wt = ssw[t * CH + q * 16 + c];
            acc[t].x += v.x * wt; acc[t].y += v.y * wt;
            acc[t].z += v.z * wt; acc[t].w += v.w * wt;
        }
    }
    #pragma unroll
    for (int t = 0; t < TAPS; t++) sp[q][t][w4] = acc[t];
    __syncthreads();
    int w = tid;                                  // 0..191
    const float* spf = reinterpret_cast<const float*>(sp);
    float f[TAPS];
    #pragma unroll
    for (int t = 0; t < TAPS; t++)
        f[t] = ssb[t] + spf[(0 * TAPS + t) * 192 + w] + spf[(1 * TAPS + t) * 192 + w]
                      + spf[(2 * TAPS + t) * 192 + w] + spf[(3 * TAPS + t) * 192 + w];
    float mean = 0.f;
    #pragma unroll
    for (int t = 0; t < TAPS; t++) mean += f[t];
    mean *= (1.f / 9.f);
    float var = 0.f;
    #pragma unroll
    for (int t = 0; t < TAPS; t++) { float d = f[t] - mean; var += d * d; }
    var *= (1.f / 8.f);
    float inv = STDV / (sqrtf(var) + 1e-10f);
    size_t hw = (size_t)h * WW + w;
    #pragma unroll
    for (int t = 0; t < TAPS; t++)
        g_s[((size_t)(b * TAPS + t)) * HWSZ + hw] = (f[t] - mean) * inv;
}

// ---------------- K4: FUSED ddf + leaky + 1x9 conv + bias + residual ---------
// Per (b,h) block. Phase A: warp-private DDF (8 ch/warp, reg ping-pong x
// prefetch, act -> half2 smem tile directly). Phase B: R7 fp16 mma.sync conv
// reading that tile; weights loaded into the region phase A used for staging.
#define WF_U32 (36 * 4 * 32 * 4)       // 18432
#define SA_U32 (32 * 200)              // 6400
#define DC_SMEM ((WF_U32 + SA_U32) * 4)   // 99328 dynamic

__device__ __forceinline__ void mma16(float* d, const uint4& a, uint32_t b0, uint32_t b1) {
    asm volatile(
        "mma.sync.aligned.m16n8k16.row.col.f32.f16.f16.f32 "
        "{%0,%1,%2,%3}, {%4,%5,%6,%7}, {%8,%9}, {%0,%1,%2,%3};"
        : "+f"(d[0]), "+f"(d[1]), "+f"(d[2]), "+f"(d[3])
        : "r"(a.x), "r"(a.y), "r"(a.z), "r"(a.w), "r"(b0), "r"(b1));
}

__global__ __launch_bounds__(256, 2)
void k_dc(const float* __restrict__ x, const float* __restrict__ b2,
          float* __restrict__ out) {
    extern __shared__ uint32_t smu[];
    uint32_t* wfu = smu;                       // phase B weights / phase A staging
    uint32_t* sau = smu + WF_U32;              // [32 c-pairs][200] half2 act tile
    __half*   sah = reinterpret_cast<__half*>(sau);
    __shared__ float ss[TAPS * WW];            // s row (fp32)
    __shared__ float scf[CH * TAPS];
    __shared__ float sbias[CH];
    const int h = blockIdx.x, b = blockIdx.y;
    const int tid = threadIdx.x;
    const int wid = tid >> 5, lane = tid & 31;

    // init: s, cf, act-tile halos
    for (int i = tid; i < TAPS * WW; i += 256)
        ss[i] = g_s[((size_t)(b * TAPS + i / WW)) * HWSZ + (size_t)h * WW + (i % WW)];
    for (int i = tid; i < CH * TAPS; i += 256) scf[i] = g_cf[b * CH * TAPS + i];
    if (tid < CH) sbias[tid] = b2[tid];
    for (int i = tid; i < SA_U32; i += 256) {
        int iw = i % 200;
        if (iw < 4 || iw >= 196) sau[i] = 0u;
    }
    __syncthreads();

    // ---- Phase A: warp-private DDF over channels wid*8 .. wid*8+7 ----
    {
        float* stgb = reinterpret_cast<float*>(wfu) + wid * 1164;  // 2 x 582 floats
        float sreg[54];                         // s[tap] for this lane's 6 w slots
        #pragma unroll
        for (int j = 0; j < 6; j++)
            #pragma unroll
            for (int t = 0; t < TAPS; t++)
                sreg[j * 9 + t] = ss[t * WW + lane + 32 * j];

        const int cbase = wid * 8;
        float rv[18];
        // preload channel cbase
        #pragma unroll
        for (int r = 0; r < 3; r++) {
            int hr = h - 1 + r;
            const float* xr = x + ((size_t)(b * CH + cbase)) * HWSZ + (size_t)hr * WW;
            #pragma unroll
            for (int j = 0; j < 6; j++)
                rv[r * 6 + j] = (hr >= 0 && hr < HH) ? xr[lane + 32 * j] : 0.f;
        }
        {
            float* stg = stgb;
            #pragma unroll
            for (int r = 0; r < 3; r++)
                #pragma unroll
                for (int j = 0; j < 6; j++)
                    stg[r * 194 + 1 + lane + 32 * j] = rv[r * 6 + j];
            if (lane < 3) { stg[lane * 194] = 0.f; stg[lane * 194 + 193] = 0.f; }
        }
        for (int ci = 0; ci < 8; ci++) {
            const int c = cbase + ci;
            float* stg = stgb + (ci & 1) * 582;
            if (ci < 7) {                        // prefetch next channel
                #pragma unroll
                for (int r = 0; r < 3; r++) {
                    int hr = h - 1 + r;
                    const float* xr = x + ((size_t)(b * CH + c + 1)) * HWSZ + (size_t)hr * WW;
                    #pragma unroll
                    for (int j = 0; j < 6; j++)
                        rv[r * 6 + j] = (hr >= 0 && hr < HH) ? xr[lane + 32 * j] : 0.f;
                }
            }
            float cfr[TAPS];
            #pragma unroll
            for (int t = 0; t < TAPS; t++) cfr[t] = scf[c * TAPS + t];
            const int c2 = c >> 1, par = c & 1;
            #pragma unroll
            for (int j = 0; j < 6; j++) {
                const int w = lane + 32 * j;
                float a = 0.f;
                #pragma unroll
                for (int t = 0; t < TAPS; t++) {
                    int i = t / 3, dj = t % 3;
                    a += stg[i * 194 + w + dj] * (sreg[j * 9 + t] * cfr[t]);
                }
                a = a >= 0.f ? a : 0.1f * a;
                sah[(c2 * 200 + w + 4) * 2 + par] = __float2half(a);
            }
            if (ci < 7) {
                float* stn = stgb + ((ci + 1) & 1) * 582;
                #pragma unroll
                for (int r = 0; r < 3; r++)
                    #pragma unroll
                    for (int j = 0; j < 6; j++)
                        stn[r * 194 + 1 + lane + 32 * j] = rv[r * 6 + j];
                if (lane < 3) { stn[lane * 194] = 0.f; stn[lane * 194 + 193] = 0.f; }
            }
        }
    }
    __syncthreads();

    // ---- load weights into wfu (staging no longer needed) ----
    {
        const uint4* src = reinterpret_cast<const uint4*>(g_wtf);
        uint4* dst = reinterpret_cast<uint4*>(wfu);
        for (int i = tid; i < WF_U32 / 4; i += 256) dst[i] = src[i];
    }
    __syncthreads();

    // ---- Phase B: fp16 mma conv (M=64, N=192, K=576) ----
    const int g = lane >> 2, t = lane & 3;
    const int mo2 = wid & 1;
    const int w0 = (wid >> 1) * 48;

    float acc[2][6][4];
    #pragma unroll
    for (int mf = 0; mf < 2; mf++)
        #pragma unroll
        for (int j = 0; j < 6; j++)
            #pragma unroll
            for (int r = 0; r < 4; r++) acc[mf][j][r] = 0.f;

    for (int tap = 0; tap < TAPS; tap++) {
        #pragma unroll
        for (int cc = 0; cc < 4; cc++) {
            const int ks = tap * 4 + cc;
            const uint4* wp = reinterpret_cast<const uint4*>(
                wfu + ((ks * 4 + mo2 * 2) * 32 + lane) * 4);
            uint4 a0 = wp[0];
            uint4 a1 = wp[32];
            const uint32_t* pb0 = sau + (cc * 8 + t) * 200 + (w0 + g + tap);
            const uint32_t* pb1 = pb0 + 4 * 200;
            #pragma unroll
            for (int j = 0; j < 6; j++) {
                uint32_t bb0 = pb0[8 * j];
                uint32_t bb1 = pb1[8 * j];
                mma16(acc[0][j], a0, bb0, bb1);
                mma16(acc[1][j], a1, bb0, bb1);
            }
        }
    }

    // epilogue: residual + bias
    const size_t rbase = ((size_t)b * CH) * HWSZ + (size_t)h * WW;
    #pragma unroll
    for (int mf = 0; mf < 2; mf++) {
        const int o = mo2 * 32 + mf * 16 + g;
        #pragma unroll
        for (int j = 0; j < 6; j++) {
            const int w = w0 + 8 * j + 2 * t;
            size_t i0 = rbase + (size_t)o * HWSZ + w;
            float2 xv = *reinterpret_cast<const float2*>(x + i0);
            float2 r0;
            r0.x = xv.x + sbias[o] + acc[mf][j][0];
            r0.y = xv.y + sbias[o] + acc[mf][j][1];
            *reinterpret_cast<float2*>(out + i0) = r0;
            size_t i1 = i0 + (size_t)8 * HWSZ;
            float2 xv1 = *reinterpret_cast<const float2*>(x + i1);
            float2 r1;
            r1.x = xv1.x + sbias[o + 8] + acc[mf][j][2];
            r1.y = xv1.y + sbias[o + 8] + acc[mf][j][3];
            *reinterpret_cast<float2*>(out + i1) = r1;
        }
    }
}

// ---------------- launch ------------------------------------------------------
extern "C" void kernel_launch(void* const* d_in, const int* in_sizes, int n_in,
                              void* d_out, int out_size) {
    const float* x   = (const float*)d_in[0];
    const float* sw  = (const float*)d_in[1];
    const float* sb  = (const float*)d_in[2];
    const float* cw1 = (const float*)d_in[3];
    const float* cb1 = (const float*)d_in[4];
    const float* cw2 = (const float*)d_in[5];
    const float* cb2 = (const float*)d_in[6];
    const float* w2  = (const float*)d_in[7];
    const float* b2  = (const float*)d_in[8];
    float* out = (float*)d_out;

    cudaFuncSetAttribute(k_dc, cudaFuncAttributeMaxDynamicSharedMemorySize, DC_SMEM);

    k_wprep<<<72, 256>>>(w2);
    k_gap<<<dim3(BATCH * CH, 4), 256>>>(x);
    k_cf<<<1, 256>>>(cw1, cb1, cw2, cb2);
    k_spatial<<<dim3(HH, BATCH), 192>>>(x, sw, sb);
    k_dc<<<dim3(HH, BATCH), 256, DC_SMEM>>>(x, b2, out);
}

// round 10
// speedup vs baseline: 4.3300x; 1.0683x over previous
#include <cuda_runtime.h>
#include <cuda_bf16.h>
#include <cuda_fp16.h>
#include <cstdint>
#include <math.h>

#define BATCH 4
#define CH 64
#define HH 192
#define WW 192
#define HWSZ (HH * WW)            // 36864
#define TAPS 9
#define MID 12
#define STDV 0.4714045207910317f  // sqrt(2)/3

// ---------------- scratch (device globals; no allocation allowed) ------------
__device__ float g_gapp[4 * BATCH * CH];          // partial GAP sums
__device__ float g_cf[BATCH * CH * TAPS];
__device__ uint32_t g_wtf[36 * 4 * 32 * 4];       // fragment-ordered fp16x2 weights

// ---------------- K0: weight prep into m16n8k16 fp16 fragment order ----------
__global__ void k_wprep(const float* __restrict__ w2) {
    int idx = blockIdx.x * 256 + threadIdx.x;     // 18432 total
    if (idx >= 36 * 4 * 32 * 4) return;
    int reg  = idx & 3;
    int lane = (idx >> 2) & 31;
    int mf   = (idx >> 7) & 3;
    int ks   = idx >> 9;
    int tap = ks >> 2, cc = ks & 3;
    int g = lane >> 2, t = lane & 3;
    int o = mf * 16 + g + ((reg & 1) ? 8 : 0);
    int c = cc * 16 + 2 * t + ((reg & 2) ? 8 : 0);
    float lo = w2[(size_t)o * 576 + c * 9 + tap];
    float hi = w2[(size_t)o * 576 + (c + 1) * 9 + tap];
    __half2 hv = __halves2half2(__float2half(lo), __float2half(hi));
    g_wtf[idx] = *reinterpret_cast<uint32_t*>(&hv);
}

// ---------------- K1: partial global average pool ----------------------------
__global__ void k_gap(const float* __restrict__ x) {
    int bc = blockIdx.x, q = blockIdx.y;
    const float4* p = reinterpret_cast<const float4*>(x + (size_t)bc * HWSZ) + q * 2304;
    float s = 0.f;
    for (int i = threadIdx.x; i < 2304; i += 256) {
        float4 v = p[i];
        s += (v.x + v.y) + (v.z + v.w);
    }
    for (int o = 16; o; o >>= 1) s += __shfl_xor_sync(0xffffffffu, s, o);
    __shared__ float red[8];
    if ((threadIdx.x & 31) == 0) red[threadIdx.x >> 5] = s;
    __syncthreads();
    if (threadIdx.x == 0) {
        float t = 0.f;
        #pragma unroll
        for (int i = 0; i < 8; i++) t += red[i];
        g_gapp[q * (BATCH * CH) + bc] = t;
    }
}

// ---------------- K2: channel branch MLP + FilterNorm -> g_cf ----------------
__global__ void k_cf(const float* __restrict__ cw1, const float* __restrict__ cb1,
                     const float* __restrict__ cw2, const float* __restrict__ cb2) {
    __shared__ float gs[BATCH * CH];
    __shared__ float h1s[BATCH * MID];
    int tid = threadIdx.x;
    gs[tid] = (g_gapp[tid] + g_gapp[256 + tid] + g_gapp[512 + tid] + g_gapp[768 + tid])
              * (1.f / (float)HWSZ);
    __syncthreads();
    if (tid < BATCH * MID) {
        int b = tid / MID, m = tid % MID;
        float a = cb1[m];
        for (int j = 0; j < CH; j++) a += gs[b * CH + j] * cw1[m * CH + j];
        h1s[tid] = a > 0.f ? a : 0.f;
    }
    __syncthreads();
    int b = tid >> 6, c = tid & 63;
    float f[TAPS];
    #pragma unroll
    for (int t = 0; t < TAPS; t++) {
        float a = cb2[c * TAPS + t];
        #pragma unroll
        for (int m = 0; m < MID; m++) a += h1s[b * MID + m] * cw2[(c * TAPS + t) * MID + m];
        f[t] = a;
    }
    float mean = 0.f;
    #pragma unroll
    for (int t = 0; t < TAPS; t++) mean += f[t];
    mean *= (1.f / 9.f);
    float var = 0.f;
    #pragma unroll
    for (int t = 0; t < TAPS; t++) { float d = f[t] - mean; var += d * d; }
    var *= (1.f / 8.f);
    float inv = STDV / (sqrtf(var) + 1e-10f);
    #pragma unroll
    for (int t = 0; t < TAPS; t++) g_cf[tid * TAPS + t] = (f[t] - mean) * inv;
}

// ---------------- K3: FULLY FUSED spatial + ddf + leaky + conv + residual ----
// Per (b,h) block:
//   A0: warp-partial 1x1-conv spatial filters (8 ch/warp) -> partials in wfu
//   reduce: bias + FilterNorm -> ss[9][192]
//   A:  warp-private DDF (reg ping-pong x prefetch) -> half2 act tile sau
//   B:  fp16 mma.sync 1x9 conv (M=64,N=192,K=576) + bias + residual
#define WF_U32 (36 * 4 * 32 * 4)       // 18432
#define SA_U32 (32 * 200)              // 6400
#define DC_SMEM ((WF_U32 + SA_U32) * 4)   // 99328 dynamic

__device__ __forceinline__ void mma16(float* d, const uint4& a, uint32_t b0, uint32_t b1) {
    asm volatile(
        "mma.sync.aligned.m16n8k16.row.col.f32.f16.f16.f32 "
        "{%0,%1,%2,%3}, {%4,%5,%6,%7}, {%8,%9}, {%0,%1,%2,%3};"
        : "+f"(d[0]), "+f"(d[1]), "+f"(d[2]), "+f"(d[3])
        : "r"(a.x), "r"(a.y), "r"(a.z), "r"(a.w), "r"(b0), "r"(b1));
}

__global__ __launch_bounds__(256, 2)
void k_dc(const float* __restrict__ x, const float* __restrict__ sw,
          const float* __restrict__ sbv, const float* __restrict__ b2,
          float* __restrict__ out) {
    extern __shared__ uint32_t smu[];
    uint32_t* wfu = smu;                       // A0 partials / A staging / B weights
    float*    wfu_f = reinterpret_cast<float*>(wfu);
    uint32_t* sau = smu + WF_U32;              // A0: sw staging; later half2 act tile
    __half*   sah = reinterpret_cast<__half*>(sau);
    __shared__ float ss[TAPS * WW];            // normalized s row
    __shared__ float scf[CH * TAPS];
    __shared__ float sbias[CH];
    __shared__ float ssb[TAPS];
    const int h = blockIdx.x, b = blockIdx.y;
    const int tid = threadIdx.x;
    const int wid = tid >> 5, lane = tid & 31;

    // init: cf, biases, sw (staged in sau region — dead until halos)
    for (int i = tid; i < CH * TAPS; i += 256) scf[i] = g_cf[b * CH * TAPS + i];
    if (tid < CH) sbias[tid] = b2[tid];
    if (tid < TAPS) ssb[tid] = sbv[tid];
    float* ssw_tmp = reinterpret_cast<float*>(sau);
    for (int i = tid; i < TAPS * CH; i += 256) ssw_tmp[i] = sw[i];
    __syncthreads();

    // ---- Phase A0: warp-partial spatial filter sums over 8 channels ----
    {
        float part[54];
        #pragma unroll
        for (int i = 0; i < 54; i++) part[i] = 0.f;
        const int cbase = wid * 8;
        #pragma unroll
        for (int ci = 0; ci < 8; ci++) {
            const float* xr = x + ((size_t)(b * CH + cbase + ci)) * HWSZ + (size_t)h * WW;
            float swc[TAPS];
            #pragma unroll
            for (int t = 0; t < TAPS; t++) swc[t] = ssw_tmp[t * CH + cbase + ci];
            #pragma unroll
            for (int j = 0; j < 6; j++) {
                float v = xr[lane + 32 * j];
                #pragma unroll
                for (int t = 0; t < TAPS; t++) part[j * 9 + t] += v * swc[t];
            }
        }
        float* pf = wfu_f + wid * 1728;
        #pragma unroll
        for (int j = 0; j < 6; j++)
            #pragma unroll
            for (int t = 0; t < TAPS; t++)
                pf[t * WW + lane + 32 * j] = part[j * 9 + t];
    }
    __syncthreads();

    // ---- s reduce + FilterNorm -> ss; concurrently write act-tile halos ----
    for (int i = tid; i < SA_U32; i += 256) {
        int iw = i % 200;
        if (iw < 4 || iw >= 196) sau[i] = 0u;
    }
    if (tid < WW) {
        float f[TAPS];
        #pragma unroll
        for (int t = 0; t < TAPS; t++) f[t] = ssb[t];
        #pragma unroll
        for (int wd = 0; wd < 8; wd++) {
            const float* pf = wfu_f + wd * 1728;
            #pragma unroll
            for (int t = 0; t < TAPS; t++) f[t] += pf[t * WW + tid];
        }
        float mean = 0.f;
        #pragma unroll
        for (int t = 0; t < TAPS; t++) mean += f[t];
        mean *= (1.f / 9.f);
        float var = 0.f;
        #pragma unroll
        for (int t = 0; t < TAPS; t++) { float d = f[t] - mean; var += d * d; }
        var *= (1.f / 8.f);
        float inv = STDV / (sqrtf(var) + 1e-10f);
        #pragma unroll
        for (int t = 0; t < TAPS; t++) ss[t * WW + tid] = (f[t] - mean) * inv;
    }
    __syncthreads();

    // ---- Phase A: warp-private DDF over channels wid*8 .. wid*8+7 ----
    {
        float* stgb = wfu_f + wid * 1164;      // 2 x 582 floats ping-pong
        float sreg[54];
        #pragma unroll
        for (int j = 0; j < 6; j++)
            #pragma unroll
            for (int t = 0; t < TAPS; t++)
                sreg[j * 9 + t] = ss[t * WW + lane + 32 * j];

        const int cbase = wid * 8;
        float rv[18];
        #pragma unroll
        for (int r = 0; r < 3; r++) {
            int hr = h - 1 + r;
            const float* xr = x + ((size_t)(b * CH + cbase)) * HWSZ + (size_t)hr * WW;
            #pragma unroll
            for (int j = 0; j < 6; j++)
                rv[r * 6 + j] = (hr >= 0 && hr < HH) ? xr[lane + 32 * j] : 0.f;
        }
        {
            float* stg = stgb;
            #pragma unroll
            for (int r = 0; r < 3; r++)
                #pragma unroll
                for (int j = 0; j < 6; j++)
                    stg[r * 194 + 1 + lane + 32 * j] = rv[r * 6 + j];
            if (lane < 3) { stg[lane * 194] = 0.f; stg[lane * 194 + 193] = 0.f; }
        }
        for (int ci = 0; ci < 8; ci++) {
            const int c = cbase + ci;
            float* stg = stgb + (ci & 1) * 582;
            if (ci < 7) {
                #pragma unroll
                for (int r = 0; r < 3; r++) {
                    int hr = h - 1 + r;
                    const float* xr = x + ((size_t)(b * CH + c + 1)) * HWSZ + (size_t)hr * WW;
                    #pragma unroll
                    for (int j = 0; j < 6; j++)
                        rv[r * 6 + j] = (hr >= 0 && hr < HH) ? xr[lane + 32 * j] : 0.f;
                }
            }
            float cfr[TAPS];
            #pragma unroll
            for (int t = 0; t < TAPS; t++) cfr[t] = scf[c * TAPS + t];
            const int c2 = c >> 1, par = c & 1;
            #pragma unroll
            for (int j = 0; j < 6; j++) {
                const int w = lane + 32 * j;
                float a = 0.f;
                #pragma unroll
                for (int t = 0; t < TAPS; t++) {
                    int i = t / 3, dj = t % 3;
                    a += stg[i * 194 + w + dj] * (sreg[j * 9 + t] * cfr[t]);
                }
                a = a >= 0.f ? a : 0.1f * a;
                sah[(c2 * 200 + w + 4) * 2 + par] = __float2half(a);
            }
            if (ci < 7) {
                float* stn = stgb + ((ci + 1) & 1) * 582;
                #pragma unroll
                for (int r = 0; r < 3; r++)
                    #pragma unroll
                    for (int j = 0; j < 6; j++)
                        stn[r * 194 + 1 + lane + 32 * j] = rv[r * 6 + j];
                if (lane < 3) { stn[lane * 194] = 0.f; stn[lane * 194 + 193] = 0.f; }
            }
        }
    }
    __syncthreads();

    // ---- load weights into wfu (staging/partials dead) ----
    {
        const uint4* src = reinterpret_cast<const uint4*>(g_wtf);
        uint4* dst = reinterpret_cast<uint4*>(wfu);
        for (int i = tid; i < WF_U32 / 4; i += 256) dst[i] = src[i];
    }
    __syncthreads();

    // ---- Phase B: fp16 mma conv (M=64, N=192, K=576) ----
    const int g = lane >> 2, t = lane & 3;
    const int mo2 = wid & 1;
    const int w0 = (wid >> 1) * 48;

    float acc[2][6][4];
    #pragma unroll
    for (int mf = 0; mf < 2; mf++)
        #pragma unroll
        for (int j = 0; j < 6; j++)
            #pragma unroll
            for (int r = 0; r < 4; r++) acc[mf][j][r] = 0.f;

    for (int tap = 0; tap < TAPS; tap++) {
        #pragma unroll
        for (int cc = 0; cc < 4; cc++) {
            const int ks = tap * 4 + cc;
            const uint4* wp = reinterpret_cast<const uint4*>(
                wfu + ((ks * 4 + mo2 * 2) * 32 + lane) * 4);
            uint4 a0 = wp[0];
            uint4 a1 = wp[32];
            const uint32_t* pb0 = sau + (cc * 8 + t) * 200 + (w0 + g + tap);
            const uint32_t* pb1 = pb0 + 4 * 200;
            #pragma unroll
            for (int j = 0; j < 6; j++) {
                uint32_t bb0 = pb0[8 * j];
                uint32_t bb1 = pb1[8 * j];
                mma16(acc[0][j], a0, bb0, bb1);
                mma16(acc[1][j], a1, bb0, bb1);
            }
        }
    }

    // epilogue: residual + bias
    const size_t rbase = ((size_t)b * CH) * HWSZ + (size_t)h * WW;
    #pragma unroll
    for (int mf = 0; mf < 2; mf++) {
        const int o = mo2 * 32 + mf * 16 + g;
        #pragma unroll
        for (int j = 0; j < 6; j++) {
            const int w = w0 + 8 * j + 2 * t;
            size_t i0 = rbase + (size_t)o * HWSZ + w;
            float2 xv = *reinterpret_cast<const float2*>(x + i0);
            float2 r0;
            r0.x = xv.x + sbias[o] + acc[mf][j][0];
            r0.y = xv.y + sbias[o] + acc[mf][j][1];
            *reinterpret_cast<float2*>(out + i0) = r0;
            size_t i1 = i0 + (size_t)8 * HWSZ;
            float2 xv1 = *reinterpret_cast<const float2*>(x + i1);
            float2 r1;
            r1.x = xv1.x + sbias[o + 8] + acc[mf][j][2];
            r1.y = xv1.y + sbias[o + 8] + acc[mf][j][3];
            *reinterpret_cast<float2*>(out + i1) = r1;
        }
    }
}

// ---------------- launch ------------------------------------------------------
extern "C" void kernel_launch(void* const* d_in, const int* in_sizes, int n_in,
                              void* d_out, int out_size) {
    const float* x   = (const float*)d_in[0];
    const float* sw  = (const float*)d_in[1];
    const float* sb  = (const float*)d_in[2];
    const float* cw1 = (const float*)d_in[3];
    const float* cb1 = (const float*)d_in[4];
    const float* cw2 = (const float*)d_in[5];
    const float* cb2 = (const float*)d_in[6];
    const float* w2  = (const float*)d_in[7];
    const float* b2  = (const float*)d_in[8];
    float* out = (float*)d_out;

    cudaFuncSetAttribute(k_dc, cudaFuncAttributeMaxDynamicSharedMemorySize, DC_SMEM);

    k_wprep<<<72, 256>>>(w2);
    k_gap<<<dim3(BATCH * CH, 4), 256>>>(x);
    k_cf<<<1, 256>>>(cw1, cb1, cw2, cb2);
    k_dc<<<dim3(HH, BATCH), 256, DC_SMEM>>>(x, sw, sb, b2, out);
}